// round 5
// baseline (speedup 1.0000x reference)
#include <cuda_runtime.h>
#include <cuda_fp16.h>
#include <cstdint>

// Shapes (fixed)
#define N_NODES 8192
#define D_IN    200
#define D_OUT   128
#define NEG_SLOPE 0.01f

// K3 tiling
#define BM      64              // M rows per CTA
#define BKC     64              // K per pipeline chunk (64 fp16 = 128B rows)
#define NCHUNKS (N_NODES / BKC) // 128
#define STAGES  4
#define A_TILE_B  (BM * BKC * 2)        // 8 KB
#define B_TILE_B  (D_OUT * BKC * 2)     // 16 KB
#define STAGE_B   (A_TILE_B + B_TILE_B) // 24 KB
#define SWZ(off) ((off) ^ (((off) >> 3) & 0x70))

// Scratch (__device__ globals: allocation-free rule)
__device__ float  g_dis[N_NODES];                       // d^{-1/2}
__device__ __half g_Ah[(size_t)N_NODES * N_NODES];      // fp16 copy of A'
__device__ __half g_Bt[(size_t)D_OUT * N_NODES];        // [n][k] fp16 dis[k]*(HW+b)

// ---------------------------------------------------------------------------
// Kernel 1: A' = max(sigmoid(A), 0.1) -> fp32 output + fp16 copy; rowsum->rsqrt
// ---------------------------------------------------------------------------
__global__ void __launch_bounds__(256) k_sigmoid_rowsum(
    const float* __restrict__ A, float* __restrict__ Aout)
{
    const int row = blockIdx.x;
    const float4* ap = reinterpret_cast<const float4*>(A + (size_t)row * N_NODES);
    float4* op = reinterpret_cast<float4*>(Aout + (size_t)row * N_NODES);
    uint2* hp = reinterpret_cast<uint2*>(g_Ah + (size_t)row * N_NODES);

    float sum = 0.0f;
    #pragma unroll 2
    for (int i = threadIdx.x; i < N_NODES / 4; i += 256) {
        float4 v = ap[i];
        float4 s;
        s.x = fmaxf(__fdividef(1.0f, 1.0f + __expf(-v.x)), 0.1f);
        s.y = fmaxf(__fdividef(1.0f, 1.0f + __expf(-v.y)), 0.1f);
        s.z = fmaxf(__fdividef(1.0f, 1.0f + __expf(-v.z)), 0.1f);
        s.w = fmaxf(__fdividef(1.0f, 1.0f + __expf(-v.w)), 0.1f);
        op[i] = s;
        __half2 p0 = __floats2half2_rn(s.x, s.y);
        __half2 p1 = __floats2half2_rn(s.z, s.w);
        uint2 u;
        u.x = *reinterpret_cast<uint32_t*>(&p0);
        u.y = *reinterpret_cast<uint32_t*>(&p1);
        hp[i] = u;
        sum += (s.x + s.y) + (s.z + s.w);
    }

    #pragma unroll
    for (int off = 16; off > 0; off >>= 1)
        sum += __shfl_xor_sync(0xFFFFFFFFu, sum, off);

    __shared__ float ws[8];
    const int wid = threadIdx.x >> 5;
    const int lane = threadIdx.x & 31;
    if (lane == 0) ws[wid] = sum;
    __syncthreads();
    if (threadIdx.x == 0) {
        float tot = 0.0f;
        #pragma unroll
        for (int w = 0; w < 8; w++) tot += ws[w];
        g_dis[row] = rsqrtf(tot);
    }
}

// ---------------------------------------------------------------------------
// Kernel 2 (rewritten): g_Bt[j][k] = fp16( dis[k] * (H[k,:]@W[:,j] + b[j]) )
// 512 blocks x 256 thr. Block tile: 16 k-rows x 128 j. Thread: 2k x 4j.
// W via float4 LDG (L1-resident, 8 FMA per load); H via smem broadcast.
// ---------------------------------------------------------------------------
#define K2_ROWS 16
__global__ void __launch_bounds__(256) k_hw(
    const float* __restrict__ H, const float* __restrict__ W,
    const float* __restrict__ b)
{
    __shared__ float hs[K2_ROWS][D_IN];
    const int kb = blockIdx.x * K2_ROWS;
    const int tid = threadIdx.x;

    // stage H tile (16 rows x 200 floats, float4)
    for (int idx = tid; idx < K2_ROWS * (D_IN / 4); idx += 256) {
        const int r = idx / (D_IN / 4), c = idx % (D_IN / 4);
        reinterpret_cast<float4*>(&hs[r][0])[c] =
            reinterpret_cast<const float4*>(H + (size_t)(kb + r) * D_IN)[c];
    }
    __syncthreads();

    const int ty = tid >> 5;          // 0..7  -> k pair
    const int tx = tid & 31;          // 0..31 -> j group
    const int j0 = tx * 4;
    const int k0 = kb + ty * 2;

    const float4 bj = *reinterpret_cast<const float4*>(b + j0);
    float4 acc0 = bj, acc1 = bj;
    const float* h0p = hs[ty * 2];
    const float* h1p = hs[ty * 2 + 1];

    #pragma unroll 4
    for (int i = 0; i < D_IN; i++) {
        const float4 w4 = *reinterpret_cast<const float4*>(W + i * D_OUT + j0);
        const float h0 = h0p[i];
        const float h1 = h1p[i];
        acc0.x = fmaf(h0, w4.x, acc0.x);
        acc0.y = fmaf(h0, w4.y, acc0.y);
        acc0.z = fmaf(h0, w4.z, acc0.z);
        acc0.w = fmaf(h0, w4.w, acc0.w);
        acc1.x = fmaf(h1, w4.x, acc1.x);
        acc1.y = fmaf(h1, w4.y, acc1.y);
        acc1.z = fmaf(h1, w4.z, acc1.z);
        acc1.w = fmaf(h1, w4.w, acc1.w);
    }

    const float d0 = g_dis[k0];
    const float d1 = g_dis[k0 + 1];
    // transposed half2 stores: g_Bt[j][k0], k0 even -> 4B aligned
    __half2 p;
    p = __floats2half2_rn(acc0.x * d0, acc1.x * d1);
    *reinterpret_cast<__half2*>(&g_Bt[(size_t)(j0 + 0) * N_NODES + k0]) = p;
    p = __floats2half2_rn(acc0.y * d0, acc1.y * d1);
    *reinterpret_cast<__half2*>(&g_Bt[(size_t)(j0 + 1) * N_NODES + k0]) = p;
    p = __floats2half2_rn(acc0.z * d0, acc1.z * d1);
    *reinterpret_cast<__half2*>(&g_Bt[(size_t)(j0 + 2) * N_NODES + k0]) = p;
    p = __floats2half2_rn(acc0.w * d0, acc1.w * d1);
    *reinterpret_cast<__half2*>(&g_Bt[(size_t)(j0 + 3) * N_NODES + k0]) = p;
}

// ---------------------------------------------------------------------------
// K3: fp16 HMMA GEMM. 128 CTAs (M=64 each), N=128 full, K=8192.
// cp.async 4-stage pipeline, ldmatrix, mma.m16n8k16.f16.f32.
// Warp grid 2(m)x4(n): warp tile 32x32.
// ---------------------------------------------------------------------------
__device__ __forceinline__ uint32_t s2u(const void* p) {
    uint32_t a;
    asm("{ .reg .u64 t; cvta.to.shared.u64 t, %1; cvt.u32.u64 %0, t; }"
        : "=r"(a) : "l"(p));
    return a;
}
__device__ __forceinline__ void cp16(uint32_t dst, const void* src) {
    asm volatile("cp.async.cg.shared.global [%0], [%1], 16;"
                 :: "r"(dst), "l"(src) : "memory");
}
__device__ __forceinline__ void ldsm4(uint32_t* r, uint32_t addr) {
    asm volatile("ldmatrix.sync.aligned.m8n8.x4.shared.b16 {%0,%1,%2,%3}, [%4];"
                 : "=r"(r[0]), "=r"(r[1]), "=r"(r[2]), "=r"(r[3]) : "r"(addr));
}
__device__ __forceinline__ void hmma(float* d, const uint32_t* a,
                                     uint32_t b0, uint32_t b1) {
    asm volatile(
        "mma.sync.aligned.m16n8k16.row.col.f32.f16.f16.f32 "
        "{%0,%1,%2,%3},{%4,%5,%6,%7},{%8,%9},{%0,%1,%2,%3};"
        : "+f"(d[0]), "+f"(d[1]), "+f"(d[2]), "+f"(d[3])
        : "r"(a[0]), "r"(a[1]), "r"(a[2]), "r"(a[3]), "r"(b0), "r"(b1));
}

__global__ void __launch_bounds__(256, 1) k_gemm_h(float* __restrict__ out)
{
    extern __shared__ __align__(1024) char dsm[];   // STAGES * 24KB = 96KB
    const int t   = threadIdx.x;
    const int wid = t >> 5, lane = t & 31;
    const int wm  = wid & 1;          // m slab (0..1) * 32
    const int wn  = wid >> 1;         // n slab (0..3) * 32
    const int m0  = blockIdx.x * BM;
    const uint32_t smBase = s2u(dsm);

    // ---- staging maps (per thread): 16B chunks, rows of 128B with XOR swizzle
    const int sr  = t >> 3;           // 0..31
    const int sc  = (t & 7) * 16;     // byte col in 128B row
    const __half* srcA = g_Ah + (size_t)(m0 + sr) * N_NODES + (t & 7) * 8;
    const __half* srcB = g_Bt + (size_t)sr * N_NODES + (t & 7) * 8;
    const uint32_t dstA = SWZ(sr * 128 + sc);           // + 4096 for rows+32
    const uint32_t dstB = SWZ(sr * 128 + sc);           // + 4096 per 32 rows

    // ---- ldmatrix address components (row fixed per fragment)
    const int lr16 = lane & 15;
    const int lhalf = (lane >> 4) * 16;   // 16B col select
    uint32_t aBase[2], bBase[2];
    #pragma unroll
    for (int mt = 0; mt < 2; mt++) {
        int r = wm * 32 + mt * 16 + lr16;
        aBase[mt] = r * 128 + lhalf;      // SWZ applied after adding kk*32
    }
    #pragma unroll
    for (int bt = 0; bt < 2; bt++) {
        int r = wn * 32 + bt * 16 + lr16;
        bBase[bt] = r * 128 + lhalf;
    }

    float acc[2][4][4];
    #pragma unroll
    for (int mt = 0; mt < 2; mt++)
        #pragma unroll
        for (int nt = 0; nt < 4; nt++)
            #pragma unroll
            for (int r = 0; r < 4; r++) acc[mt][nt][r] = 0.0f;

    // ---- prologue: issue STAGES-1 chunks
    #pragma unroll
    for (int c = 0; c < STAGES - 1; c++) {
        const uint32_t sA = smBase + c * STAGE_B;
        const uint32_t sB = sA + A_TILE_B;
        const int ko = c * BKC;
        cp16(sA + dstA,        srcA + ko);
        cp16(sA + dstA + 4096, srcA + ko + 32ull * N_NODES);
        #pragma unroll
        for (int rb = 0; rb < 4; rb++)
            cp16(sB + dstB + rb * 4096, srcB + ko + (size_t)rb * 32 * N_NODES);
        asm volatile("cp.async.commit_group;" ::: "memory");
    }

    for (int c = 0; c < NCHUNKS; c++) {
        asm volatile("cp.async.wait_group %0;" :: "n"(STAGES - 2) : "memory");
        __syncthreads();

        const uint32_t sA = smBase + (c & (STAGES - 1)) * STAGE_B;
        const uint32_t sB = sA + A_TILE_B;

        #pragma unroll
        for (int kk = 0; kk < BKC / 16; kk++) {
            uint32_t aF[2][4], bF[2][4];
            #pragma unroll
            for (int mt = 0; mt < 2; mt++)
                ldsm4(aF[mt], sA + SWZ(aBase[mt] + kk * 32));
            #pragma unroll
            for (int bt = 0; bt < 2; bt++)
                ldsm4(bF[bt], sB + SWZ(bBase[bt] + kk * 32));
            #pragma unroll
            for (int mt = 0; mt < 2; mt++)
                #pragma unroll
                for (int nt = 0; nt < 4; nt++)
                    hmma(acc[mt][nt], aF[mt],
                         bF[nt >> 1][nt & 1], bF[nt >> 1][(nt & 1) + 2]);
        }

        // issue chunk c + STAGES-1
        const int cn = c + STAGES - 1;
        if (cn < NCHUNKS) {
            const uint32_t nA = smBase + (cn & (STAGES - 1)) * STAGE_B;
            const uint32_t nB = nA + A_TILE_B;
            const int ko = cn * BKC;
            cp16(nA + dstA,        srcA + ko);
            cp16(nA + dstA + 4096, srcA + ko + 32ull * N_NODES);
            #pragma unroll
            for (int rb = 0; rb < 4; rb++)
                cp16(nB + dstB + rb * 4096, srcB + ko + (size_t)rb * 32 * N_NODES);
        }
        asm volatile("cp.async.commit_group;" ::: "memory");
    }

    // ---- epilogue: scale by dis[i], LeakyReLU, store float2 pairs
    const int gid = lane >> 2;          // 0..7
    const int cid = (lane & 3) * 2;     // 0,2,4,6
    #pragma unroll
    for (int mt = 0; mt < 2; mt++) {
        const int r0 = m0 + wm * 32 + mt * 16 + gid;
        const float d0 = g_dis[r0];
        const float d1 = g_dis[r0 + 8];
        #pragma unroll
        for (int nt = 0; nt < 4; nt++) {
            const int col = wn * 32 + nt * 8 + cid;
            float v0 = d0 * acc[mt][nt][0];
            float v1 = d0 * acc[mt][nt][1];
            float v2 = d1 * acc[mt][nt][2];
            float v3 = d1 * acc[mt][nt][3];
            v0 = (v0 >= 0.0f) ? v0 : NEG_SLOPE * v0;
            v1 = (v1 >= 0.0f) ? v1 : NEG_SLOPE * v1;
            v2 = (v2 >= 0.0f) ? v2 : NEG_SLOPE * v2;
            v3 = (v3 >= 0.0f) ? v3 : NEG_SLOPE * v3;
            *reinterpret_cast<float2*>(out + (size_t)r0 * D_OUT + col)
                = make_float2(v0, v1);
            *reinterpret_cast<float2*>(out + (size_t)(r0 + 8) * D_OUT + col)
                = make_float2(v2, v3);
        }
    }
}

// ---------------------------------------------------------------------------
extern "C" void kernel_launch(void* const* d_in, const int* in_sizes, int n_in,
                              void* d_out, int out_size)
{
    const float* H = (const float*)d_in[0];   // [8192, 200]
    const float* A = (const float*)d_in[1];   // [8192, 8192]
    const float* W = (const float*)d_in[2];   // [200, 128]
    const float* b = (const float*)d_in[3];   // [128]

    float* out  = (float*)d_out;                     // [8192, 128]
    float* Aout = out + (size_t)N_NODES * D_OUT;     // [8192, 8192] exact A'

    k_sigmoid_rowsum<<<N_NODES, 256>>>(A, Aout);
    k_hw<<<N_NODES / K2_ROWS, 256>>>(H, W, b);

    cudaFuncSetAttribute(k_gemm_h, cudaFuncAttributeMaxDynamicSharedMemorySize,
                         STAGES * STAGE_B);
    k_gemm_h<<<N_NODES / BM, 256, STAGES * STAGE_B>>>(out);
}